// round 15
// baseline (speedup 1.0000x reference)
#include <cuda_runtime.h>
#include <cstdint>

// ---------------- problem constants ----------------
#define NB 1024
#define NT 128
#define ND 256
#define NH 128
#define NG 512
#define NK 640
#define NCTA 128

typedef unsigned long long ull;
typedef ulonglong2 ull2;

// ---------------- f32x2 packed math ----------------
__device__ __forceinline__ ull ffma2(ull a, ull b, ull c) {
    ull d;
    asm("fma.rn.f32x2 %0, %1, %2, %3;" : "=l"(d) : "l"(a), "l"(b), "l"(c));
    return d;
}
__device__ __forceinline__ float2 unpack2(ull v) {
    float2 r; asm("mov.b64 {%0, %1}, %2;" : "=f"(r.x), "=f"(r.y) : "l"(v)); return r;
}
__device__ __forceinline__ float sig_fast(float x) { return 1.0f / (1.0f + __expf(-x)); }
__device__ __forceinline__ float tanh_fast(float x) { return 2.0f / (1.0f + __expf(-2.0f * x)) - 1.0f; }

__device__ __forceinline__ unsigned smem_u32(const void* p) {
    unsigned r;
    asm("{ .reg .u64 t; cvta.to.shared.u64 t, %1; cvt.u32.u64 %0, t; }" : "=r"(r) : "l"(p));
    return r;
}
#define CP16(dst, src) asm volatile("cp.async.cg.shared.global [%0], [%1], 16;" :: "r"(dst), "l"(src))
#define CP_COMMIT()    asm volatile("cp.async.commit_group;")
#define CP_WAIT1()     asm volatile("cp.async.wait_group 1;")
#define CP_WAIT0()     asm volatile("cp.async.wait_group 0;")

// ---------------- device scratch ----------------
__device__ float g_pre[(size_t)NT * NB * NG];   // [t*NB+b][rr] gate-reordered
__device__ float g_Wro[NG * NK];                // row rr=4u+gate, cols [W_hh | A_0..A_3]
__device__ float g_Wxro[NG * ND];
__device__ float g_memsm[NH * NH];
__device__ float g_fA[2 * NK];
__device__ float g_h[2][NB * NH];
__device__ float g_G2[256 * NG];                // Hg @ Wcat^T  [256][512]
__device__ float g_hsum[NB * NH];
__device__ float g_biasro[NG];
__device__ float g_c0ro[NG];

// barrier state: arrive/gen on separate 256B lines
struct __align__(256) BarState {
    unsigned arrive;
    unsigned pad[63];
    unsigned gen;
    unsigned pad2[63];
};
__device__ BarState g_bar;

__device__ __forceinline__ void grid_barrier() {
    __syncthreads();
    if (threadIdx.x == 0) {
        __threadfence();
        unsigned gen = *(volatile unsigned*)&g_bar.gen;
        unsigned t = atomicAdd(&g_bar.arrive, 1u);
        if (t == (unsigned)(gridDim.x - 1)) {
            g_bar.arrive = 0;
            __threadfence();
            *(volatile unsigned*)&g_bar.gen = gen + 1;
        } else {
            while (*(volatile unsigned*)&g_bar.gen == gen) { __nanosleep(32); }
        }
        __threadfence();
    }
    __syncthreads();
}

// ---------------- 8x4 f32x2 tile (A linear, B swizzled) ----------------
__device__ __forceinline__ void slab84(const char* Ab, const char* Bb,
                                       const int aoff[8], const int boff[4],
                                       ull* acc /*32*/) {
    #pragma unroll
    for (int q = 0; q < 8; q++) {
        ull2 b[4];
        #pragma unroll
        for (int j = 0; j < 4; j++)
            b[j] = *(const ull2*)(Bb + (boff[j] ^ (q << 4)));
        #pragma unroll
        for (int i = 0; i < 8; i++) {
            ull2 a = *(const ull2*)(Ab + aoff[i] + (q << 4));
            #pragma unroll
            for (int j = 0; j < 4; j++) {
                acc[i * 4 + j] = ffma2(a.x, b[j].x, acc[i * 4 + j]);
                acc[i * 4 + j] = ffma2(a.y, b[j].y, acc[i * 4 + j]);
            }
        }
    }
}

// ---------------- 2x4 f32x2 tile ----------------
__device__ __forceinline__ void slab24(const char* Ab, const char* Bb,
                                       const int aoff[8], const int boff[4],
                                       ull* acc /*8*/) {
    #pragma unroll
    for (int q = 0; q < 8; q++) {
        ull2 b[4];
        #pragma unroll
        for (int j = 0; j < 4; j++)
            b[j] = *(const ull2*)(Bb + (boff[j] ^ (q << 4)));
        #pragma unroll
        for (int i = 0; i < 2; i++) {
            ull2 a = *(const ull2*)(Ab + aoff[i] + (q << 4));
            #pragma unroll
            for (int j = 0; j < 4; j++) {
                acc[i * 4 + j] = ffma2(a.x, b[j].x, acc[i * 4 + j]);
                acc[i * 4 + j] = ffma2(a.y, b[j].y, acc[i * 4 + j]);
            }
        }
    }
}

// ---------------- setup ----------------
__global__ void setup_kernel(const float* __restrict__ memory,
                             const float* __restrict__ b_ih,
                             const float* __restrict__ b_hh,
                             const float* __restrict__ rv0,
                             const float* __restrict__ W_ih) {
    int tid = threadIdx.x;
    float mx = -1e30f;
    for (int m = 0; m < NH; m++) mx = fmaxf(mx, memory[m * NH + tid]);
    float s = 0.f;
    for (int m = 0; m < NH; m++) s += expf(memory[m * NH + tid] - mx);
    float inv = 1.f / s;
    for (int m = 0; m < NH; m++)
        g_memsm[m * NH + tid] = expf(memory[m * NH + tid] - mx) * inv;

    for (int g = tid; g < NG; g += 128) {
        int u = g & 127, gate = g >> 7;
        int rr = 4 * u + gate;
        g_biasro[rr] = b_ih[g] + b_hh[g];
        float c0 = 0.f;
        const float* w = W_ih + (size_t)g * 768 + 256;
        for (int k = 0; k < 512; k++) c0 += rv0[k] * w[k];
        g_c0ro[rr] = c0;
    }
}

// ---------------- fold mem_sm into weights + reorder Wx ----------------
__global__ void buildA_kernel(const float* __restrict__ W_ih,
                              const float* __restrict__ W_hh,
                              const float* __restrict__ fc_w) {
    int row = blockIdx.x, q = blockIdx.y, j = threadIdx.x;
    if (q >= 5) {
        if (row < NG) {
            int u = row >> 2, gate = row & 3;
            int go = gate * 128 + u;
            g_Wxro[(size_t)row * ND + (q - 5) * 128 + j] =
                W_ih[(size_t)go * 768 + (q - 5) * 128 + j];
        }
        return;
    }
    if (row < NG) {
        int u = row >> 2, gate = row & 3;
        int go = gate * 128 + u;
        if (q == 0) {
            g_Wro[(size_t)row * NK + j] = W_hh[(size_t)go * NH + j];
        } else {
            const float* w = W_ih + (size_t)go * 768 + 256 + (q - 1) * 128;
            float s = 0.f;
            for (int m = 0; m < NH; m++) s += w[m] * g_memsm[m * NH + j];
            g_Wro[(size_t)row * NK + q * 128 + j] = s;
        }
    } else {
        int o = row - NG;
        if (q == 0) {
            g_fA[o * NK + j] = fc_w[o * NK + j];
        } else {
            const float* w = fc_w + o * NK + 128 + (q - 1) * 128;
            float s = 0.f;
            for (int m = 0; m < NH; m++) s += w[m] * g_memsm[m * NH + j];
            g_fA[o * NK + q * 128 + j] = s;
        }
    }
}

// ---------------- pre: [NT*NB,256] x [256,512] -> g_pre ----------------
__global__ __launch_bounds__(256, 2)
void pre_kernel(const float* __restrict__ x) {
    extern __shared__ char smc[];
    int r0  = blockIdx.x * 128;
    int rr0 = blockIdx.y * 64;
    int tid = threadIdx.x;
    int tx = tid & 15, ty = tid >> 4;

    int arow = tid >> 1;
    int aq0 = (tid & 1) * 4;
    int bcol = tid >> 2;
    int bq0 = (tid & 3) * 2;
    int bperm = (bcol ^ (bcol >> 3)) & 7;

    int rA = r0 + arow;
    int bb = rA & 1023, tA = rA >> 10;
    const float* xrow = x + ((size_t)bb * NT + tA) * ND;
    const float* wrow = g_Wxro + (size_t)(rr0 + bcol) * ND;
    unsigned smem_base = smem_u32(smc);

    #define PRE_ISSUE(s)                                                        \
    {                                                                           \
        unsigned stg = smem_base + ((s) % 3) * 24576u;                          \
        unsigned ab  = stg + (unsigned)(arow * 128);                            \
        unsigned bbs = stg + 16384u + (unsigned)(bcol * 128);                   \
        const float* ap = xrow + (s) * 32;                                      \
        const float* bp = wrow + (s) * 32;                                      \
        _Pragma("unroll")                                                       \
        for (int p = 0; p < 4; p++) { int qn = aq0 + p; CP16(ab + qn * 16, ap + qn * 4); } \
        _Pragma("unroll")                                                       \
        for (int p = 0; p < 2; p++) { int qn = bq0 + p; CP16(bbs + ((qn ^ bperm) << 4), bp + qn * 4); } \
        CP_COMMIT();                                                            \
    }

    int aoff[8], boff[4];
    #pragma unroll
    for (int i = 0; i < 8; i++)
        aoff[i] = (ty * 8 + i) * 128;
    #pragma unroll
    for (int j = 0; j < 4; j++) {
        int cc = tx * 4 + j;
        boff[j] = (cc * 128) ^ ((((cc ^ (cc >> 3)) & 7)) << 4);
    }

    ull acc[32];
    #pragma unroll
    for (int i = 0; i < 32; i++) acc[i] = 0ull;

    const int NS = ND / 32;
    PRE_ISSUE(0);
    PRE_ISSUE(1);
    for (int s = 0; s < NS; s++) {
        if (s + 2 < NS) { CP_WAIT1(); } else { CP_WAIT0(); }
        __syncthreads();
        if (s + 2 < NS) PRE_ISSUE(s + 2);
        const char* Ab = smc + (s % 3) * 24576;
        slab84(Ab, Ab + 16384, aoff, boff, acc);
    }
    #undef PRE_ISSUE

    int tt = r0 >> 10;
    #pragma unroll
    for (int i = 0; i < 8; i++) {
        int r = r0 + ty * 8 + i;
        int rr = rr0 + tx * 4;
        float2 s0 = unpack2(acc[i * 4 + 0]);
        float2 s1 = unpack2(acc[i * 4 + 1]);
        float2 s2 = unpack2(acc[i * 4 + 2]);
        float2 s3 = unpack2(acc[i * 4 + 3]);
        float4 v;
        v.x = s0.x + s0.y + g_biasro[rr];
        v.y = s1.x + s1.y + g_biasro[rr + 1];
        v.z = s2.x + s2.y + g_biasro[rr + 2];
        v.w = s3.x + s3.y + g_biasro[rr + 3];
        if (tt == 0) {
            v.x += g_c0ro[rr];     v.y += g_c0ro[rr + 1];
            v.z += g_c0ro[rr + 2]; v.w += g_c0ro[rr + 3];
        }
        *(float4*)(g_pre + (size_t)r * NG + rr) = v;
    }
}

// ---------------- persistent recurrence ----------------
// cta<64: G1 job (128 batches x 64 cols, K=128) + IN-REGISTER LSTM for its cells.
// cta>=64: G2 job (32 Hg-rows x 64 cols, K=512) -> store g_G2.
// smem (1KB-aligned): B @0 | A @131072 (64KB)
__global__ __launch_bounds__(256)
void recur_kernel() {
    extern __shared__ char dsm[];
    unsigned raw = smem_u32(dsm);
    unsigned db = (raw + 1023u) & ~1023u;
    char* smb = dsm + (db - raw);
    unsigned Bsm = db;
    unsigned Asm = db + 131072u;
    char* Bp = smb;
    char* Ap = smb + 131072;

    int tid = threadIdx.x;
    int cta = blockIdx.x;
    bool isG1 = cta < 64;
    int jt = isG1 ? cta : cta - 64;
    int rr0 = (jt >> 3) * 64;
    int b0 = (jt & 7) * 128;       // G1 batch tile
    int r0 = (jt & 7) * 32;        // G2 Hg-row tile
    int tx = tid & 15, ty = tid >> 4;

    // zero h0 (every CTA owns a 1KB slice)
    {
        int idx = cta * 1024 + tid * 4;
        *(float4*)(&g_h[0][idx]) = make_float4(0.f, 0.f, 0.f, 0.f);
    }

    // resident B fill (swizzled)
    {
        int nsl = isG1 ? 4 : 16;
        int koff = isG1 ? 0 : 128;
        for (int ci = tid; ci < nsl * 512; ci += 256) {
            int s = ci >> 9;
            int rem = ci & 511;
            int c = rem >> 3, qn = rem & 7;
            int perm = (c ^ (c >> 3)) & 7;
            CP16(Bsm + (unsigned)(s * 8192 + c * 128 + ((qn ^ perm) << 4)),
                 g_Wro + (size_t)(rr0 + c) * NK + koff + s * 32 + qn * 4);
        }
        CP_COMMIT(); CP_WAIT0();
    }
    grid_barrier();

    int aoff[8], boff[4];
    if (isG1) {
        #pragma unroll
        for (int i = 0; i < 8; i++)
            aoff[i] = (ty * 8 + i) * 128;
    } else {
        #pragma unroll
        for (int i = 0; i < 2; i++)
            aoff[i] = (ty * 2 + i) * 128;
    }
    #pragma unroll
    for (int j = 0; j < 4; j++) {
        int cc = tx * 4 + j;
        boff[j] = (cc * 128) ^ ((((cc ^ (cc >> 3)) & 7)) << 4);
    }

    // G1 LSTM state: thread owns unit u = rr0/4 + tx for batches b0+ty*8+0..7
    int uu = (rr0 >> 2) + tx;
    float creg[8], hsum8[8];
    #pragma unroll
    for (int i = 0; i < 8; i++) { creg[i] = 0.f; hsum8[i] = 0.f; }

    for (int t = 0; t < NT; t++) {
        const float* hb = g_h[t & 1];
        float* hn = g_h[(t + 1) & 1];

        // A fill: 64KB burst
        if (isG1) {
            #pragma unroll
            for (int i = 0; i < 16; i++) {
                int ci = i * 256 + tid;
                int s = ci >> 10, rem = ci & 1023, r = rem >> 3, qn = rem & 7;
                CP16(Asm + (unsigned)(s * 16384 + r * 128 + qn * 16),
                     hb + (size_t)(b0 + r) * NH + s * 32 + qn * 4);
            }
        } else {
            #pragma unroll
            for (int i = 0; i < 16; i++) {
                int ci = i * 256 + tid;
                int s = ci >> 8, rem = ci & 255, r = rem >> 3, qn = rem & 7;
                CP16(Asm + (unsigned)(s * 4096 + r * 128 + qn * 16),
                     hb + (size_t)r0 * 512 + r * 512 + s * 32 + qn * 4);
            }
        }
        CP_COMMIT();

        // G1: prefetch pre for my 8 cells (overlaps cp.async + GEMM)
        float pr[32];
        if (isG1) {
            #pragma unroll
            for (int i = 0; i < 8; i++)
                *(float4*)(pr + 4 * i) =
                    *(const float4*)(g_pre + ((size_t)t * NB + b0 + ty * 8 + i) * NG + rr0 + tx * 4);
        }

        CP_WAIT0();
        __syncthreads();

        if (isG1) {
            ull acc[32];
            #pragma unroll
            for (int i = 0; i < 32; i++) acc[i] = 0ull;
            #pragma unroll
            for (int s = 0; s < 4; s++)
                slab84(Ap + s * 16384, Bp + s * 8192, aoff, boff, acc);

            grid_barrier();   // wait for G2 stores

            // in-register LSTM: gates = acc + pre + G2[b&255]
            #pragma unroll
            for (int i = 0; i < 8; i++) {
                int bb = b0 + ty * 8 + i;
                float4 g2 = *(const float4*)(g_G2 + (size_t)(bb & 255) * NG + rr0 + tx * 4);
                float2 s0 = unpack2(acc[i * 4 + 0]);
                float2 s1 = unpack2(acc[i * 4 + 1]);
                float2 s2 = unpack2(acc[i * 4 + 2]);
                float2 s3 = unpack2(acc[i * 4 + 3]);
                float gi = s0.x + s0.y + pr[4 * i + 0] + g2.x;
                float gf = s1.x + s1.y + pr[4 * i + 1] + g2.y;
                float gg = s2.x + s2.y + pr[4 * i + 2] + g2.z;
                float go = s3.x + s3.y + pr[4 * i + 3] + g2.w;
                float cv = sig_fast(gf) * creg[i] + sig_fast(gi) * tanh_fast(gg);
                creg[i] = cv;
                float hv = sig_fast(go) * tanh_fast(cv);
                hsum8[i] += hv;
                hn[(size_t)bb * NH + uu] = hv;
            }
        } else {
            ull acc[8];
            #pragma unroll
            for (int i = 0; i < 8; i++) acc[i] = 0ull;
            #pragma unroll
            for (int s = 0; s < 16; s++)
                slab24(Ap + s * 4096, Bp + s * 8192, aoff, boff, acc);
            #pragma unroll
            for (int i = 0; i < 2; i++) {
                float2 s0 = unpack2(acc[i * 4 + 0]);
                float2 s1 = unpack2(acc[i * 4 + 1]);
                float2 s2 = unpack2(acc[i * 4 + 2]);
                float2 s3 = unpack2(acc[i * 4 + 3]);
                float4 v = make_float4(s0.x + s0.y, s1.x + s1.y,
                                       s2.x + s2.y, s3.x + s3.y);
                *(float4*)(g_G2 + (size_t)(r0 + ty * 2 + i) * NG + rr0 + tx * 4) = v;
            }
            grid_barrier();   // G2 stores visible; G1 runs LSTM now
        }

        grid_barrier();       // h[t+1] complete
    }

    if (isG1) {
        #pragma unroll
        for (int i = 0; i < 8; i++)
            g_hsum[(size_t)(b0 + ty * 8 + i) * NH + uu] = hsum8[i];
    }
}

// ---------------- final ----------------
__global__ void final_kernel(float* __restrict__ out, const float* __restrict__ fc_b) {
    int b = blockIdx.x * blockDim.x + threadIdx.x;
    if (b >= NB) return;
    #pragma unroll
    for (int o = 0; o < 2; o++) {
        const float* f = g_fA + o * NK;
        const float* hsp = g_hsum + b * NH;
        float s = 0.f;
        for (int k = 0; k < NH; k++) s += f[k] * hsp[k];
        #pragma unroll
        for (int q = 0; q < 4; q++) {
            const float* hq = g_hsum + ((4 * b + q) & 1023) * NH;
            const float* fq = f + 128 + q * 128;
            for (int m = 0; m < NH; m++) s += fq[m] * hq[m];
        }
        out[b * 2 + o] = fc_b[o] + s * (1.f / (float)NT);
    }
}

// ---------------- launch ----------------
extern "C" void kernel_launch(void* const* d_in, const int* in_sizes, int n_in,
                              void* d_out, int out_size) {
    const float* x      = (const float*)d_in[0];
    const float* memory = (const float*)d_in[1];
    const float* rv0    = (const float*)d_in[2];
    const float* W_ih   = (const float*)d_in[3];
    const float* W_hh   = (const float*)d_in[4];
    const float* b_ih   = (const float*)d_in[5];
    const float* b_hh   = (const float*)d_in[6];
    const float* fc_w   = (const float*)d_in[7];
    const float* fc_b   = (const float*)d_in[8];
    float* out = (float*)d_out;

    static bool attr_done = false;
    if (!attr_done) {
        cudaFuncSetAttribute(pre_kernel, cudaFuncAttributeMaxDynamicSharedMemorySize, 73728);
        cudaFuncSetAttribute(recur_kernel, cudaFuncAttributeMaxDynamicSharedMemorySize, 197632);
        attr_done = true;
    }

    setup_kernel<<<1, 128>>>(memory, b_ih, b_hh, rv0, W_ih);
    buildA_kernel<<<dim3(514, 7), 128>>>(W_ih, W_hh, fc_w);
    pre_kernel<<<dim3(NT * NB / 128, NG / 64), 256, 73728>>>(x);
    recur_kernel<<<NCTA, 256, 197632>>>();
    final_kernel<<<4, 256>>>(out, fc_b);
}

// round 16
// speedup vs baseline: 1.1100x; 1.1100x over previous
#include <cuda_runtime.h>
#include <cstdint>

// ---------------- problem constants ----------------
#define NB 1024
#define NT 128
#define ND 256
#define NH 128
#define NG 512
#define NK 640
#define NCTA 256

typedef unsigned long long ull;
typedef ulonglong2 ull2;

// ---------------- f32x2 packed math ----------------
__device__ __forceinline__ ull ffma2(ull a, ull b, ull c) {
    ull d;
    asm("fma.rn.f32x2 %0, %1, %2, %3;" : "=l"(d) : "l"(a), "l"(b), "l"(c));
    return d;
}
__device__ __forceinline__ float2 unpack2(ull v) {
    float2 r; asm("mov.b64 {%0, %1}, %2;" : "=f"(r.x), "=f"(r.y) : "l"(v)); return r;
}
__device__ __forceinline__ float sig_fast(float x) { return 1.0f / (1.0f + __expf(-x)); }
__device__ __forceinline__ float tanh_fast(float x) { return 2.0f / (1.0f + __expf(-2.0f * x)) - 1.0f; }

__device__ __forceinline__ unsigned smem_u32(const void* p) {
    unsigned r;
    asm("{ .reg .u64 t; cvta.to.shared.u64 t, %1; cvt.u32.u64 %0, t; }" : "=r"(r) : "l"(p));
    return r;
}
#define CP16(dst, src) asm volatile("cp.async.cg.shared.global [%0], [%1], 16;" :: "r"(dst), "l"(src))
#define CP_COMMIT()    asm volatile("cp.async.commit_group;")
#define CP_WAITN(n)    asm volatile("cp.async.wait_group " #n ";")
#define CP_WAIT1()     asm volatile("cp.async.wait_group 1;")
#define CP_WAIT0()     asm volatile("cp.async.wait_group 0;")

// ---------------- device scratch ----------------
__device__ float g_pre[(size_t)NT * NB * NG];   // [t*NB+b][rr] gate-reordered
__device__ float g_Wro[NG * NK];                // row rr=4u+gate, cols [W_hh | A_0..A_3]
__device__ float g_Wxro[NG * ND];
__device__ float g_memsm[NH * NH];
__device__ float g_fA[2 * NK];
__device__ float g_h[2][NB * NH];
__device__ float g_G1[(size_t)NB * NG];         // h @ W_hh^T
__device__ float g_G2p[2][256 * NG];            // K-split halves of Hg @ Wcat^T
__device__ float g_hsum[NB * NH];
__device__ float g_biasro[NG];
__device__ float g_c0ro[NG];

// barrier state: arrive/gen on separate 256B lines
struct __align__(256) BarState {
    unsigned arrive;
    unsigned pad[63];
    unsigned gen;
    unsigned pad2[63];
};
__device__ BarState g_bar;

__device__ __forceinline__ void grid_barrier() {
    __syncthreads();
    if (threadIdx.x == 0) {
        __threadfence();
        unsigned gen = *(volatile unsigned*)&g_bar.gen;
        unsigned t = atomicAdd(&g_bar.arrive, 1u);
        if (t == (unsigned)(gridDim.x - 1)) {
            g_bar.arrive = 0;
            __threadfence();
            *(volatile unsigned*)&g_bar.gen = gen + 1;
        } else {
            while (*(volatile unsigned*)&g_bar.gen == gen) { }
        }
        __threadfence();
    }
    __syncthreads();
}

// ---------------- 4x4 f32x2 tile (G1 + pre helper reuse) ----------------
__device__ __forceinline__ void slab44(const char* Ab, const char* Bb,
                                       const int aoff[4], const int boff[4],
                                       ull* acc /*16*/) {
    #pragma unroll
    for (int q = 0; q < 8; q++) {
        ull2 b[4];
        #pragma unroll
        for (int j = 0; j < 4; j++)
            b[j] = *(const ull2*)(Bb + (boff[j] ^ (q << 4)));
        #pragma unroll
        for (int i = 0; i < 4; i++) {
            ull2 a = *(const ull2*)(Ab + aoff[i] + (q << 4));
            #pragma unroll
            for (int j = 0; j < 4; j++) {
                acc[i * 4 + j] = ffma2(a.x, b[j].x, acc[i * 4 + j]);
                acc[i * 4 + j] = ffma2(a.y, b[j].y, acc[i * 4 + j]);
            }
        }
    }
}

// ---------------- 8x4 f32x2 tile (pre_kernel) ----------------
__device__ __forceinline__ void slab84(const char* Ab, const char* Bb,
                                       const int aoff[8], const int boff[4],
                                       ull* acc /*32*/) {
    #pragma unroll
    for (int q = 0; q < 8; q++) {
        ull2 b[4];
        #pragma unroll
        for (int j = 0; j < 4; j++)
            b[j] = *(const ull2*)(Bb + (boff[j] ^ (q << 4)));
        #pragma unroll
        for (int i = 0; i < 8; i++) {
            ull2 a = *(const ull2*)(Ab + aoff[i] + (q << 4));
            #pragma unroll
            for (int j = 0; j < 4; j++) {
                acc[i * 4 + j] = ffma2(a.x, b[j].x, acc[i * 4 + j]);
                acc[i * 4 + j] = ffma2(a.y, b[j].y, acc[i * 4 + j]);
            }
        }
    }
}

// ---------------- 1x8 warp-column tile (G2): lane=row, warp=8 cols ----------
__device__ __forceinline__ void slab18(const char* Ab, const char* Bb,
                                       int arow_off, int lane7, int cbase_off,
                                       ull* acc /*8*/) {
    #pragma unroll
    for (int q = 0; q < 8; q++) {
        ull2 a = *(const ull2*)(Ab + arow_off + (((q ^ lane7)) << 4));
        #pragma unroll
        for (int j = 0; j < 8; j++) {
            ull2 b = *(const ull2*)(Bb + cbase_off + j * 128 + (((q ^ j)) << 4));
            acc[j] = ffma2(a.x, b.x, acc[j]);
            acc[j] = ffma2(a.y, b.y, acc[j]);
        }
    }
}

// ---------------- setup ----------------
__global__ void setup_kernel(const float* __restrict__ memory,
                             const float* __restrict__ b_ih,
                             const float* __restrict__ b_hh,
                             const float* __restrict__ rv0,
                             const float* __restrict__ W_ih) {
    int tid = threadIdx.x;
    float mx = -1e30f;
    for (int m = 0; m < NH; m++) mx = fmaxf(mx, memory[m * NH + tid]);
    float s = 0.f;
    for (int m = 0; m < NH; m++) s += expf(memory[m * NH + tid] - mx);
    float inv = 1.f / s;
    for (int m = 0; m < NH; m++)
        g_memsm[m * NH + tid] = expf(memory[m * NH + tid] - mx) * inv;

    for (int g = tid; g < NG; g += 128) {
        int u = g & 127, gate = g >> 7;
        int rr = 4 * u + gate;
        g_biasro[rr] = b_ih[g] + b_hh[g];
        float c0 = 0.f;
        const float* w = W_ih + (size_t)g * 768 + 256;
        for (int k = 0; k < 512; k++) c0 += rv0[k] * w[k];
        g_c0ro[rr] = c0;
    }
}

// ---------------- fold mem_sm into weights + reorder Wx ----------------
__global__ void buildA_kernel(const float* __restrict__ W_ih,
                              const float* __restrict__ W_hh,
                              const float* __restrict__ fc_w) {
    int row = blockIdx.x, q = blockIdx.y, j = threadIdx.x;
    if (q >= 5) {
        if (row < NG) {
            int u = row >> 2, gate = row & 3;
            int go = gate * 128 + u;
            g_Wxro[(size_t)row * ND + (q - 5) * 128 + j] =
                W_ih[(size_t)go * 768 + (q - 5) * 128 + j];
        }
        return;
    }
    if (row < NG) {
        int u = row >> 2, gate = row & 3;
        int go = gate * 128 + u;
        if (q == 0) {
            g_Wro[(size_t)row * NK + j] = W_hh[(size_t)go * NH + j];
        } else {
            const float* w = W_ih + (size_t)go * 768 + 256 + (q - 1) * 128;
            float s = 0.f;
            for (int m = 0; m < NH; m++) s += w[m] * g_memsm[m * NH + j];
            g_Wro[(size_t)row * NK + q * 128 + j] = s;
        }
    } else {
        int o = row - NG;
        if (q == 0) {
            g_fA[o * NK + j] = fc_w[o * NK + j];
        } else {
            const float* w = fc_w + o * NK + 128 + (q - 1) * 128;
            float s = 0.f;
            for (int m = 0; m < NH; m++) s += w[m] * g_memsm[m * NH + j];
            g_fA[o * NK + q * 128 + j] = s;
        }
    }
}

// ---------------- pre: [NT*NB,256] x [256,512] -> g_pre (unchanged) ----------
__global__ __launch_bounds__(256, 2)
void pre_kernel(const float* __restrict__ x) {
    extern __shared__ char smc[];
    int r0  = blockIdx.x * 128;
    int rr0 = blockIdx.y * 64;
    int tid = threadIdx.x;
    int tx = tid & 15, ty = tid >> 4;

    int arow = tid >> 1;
    int aq0 = (tid & 1) * 4;
    int bcol = tid >> 2;
    int bq0 = (tid & 3) * 2;
    int bperm = (bcol ^ (bcol >> 3)) & 7;

    int rA = r0 + arow;
    int bb = rA & 1023, tA = rA >> 10;
    const float* xrow = x + ((size_t)bb * NT + tA) * ND;
    const float* wrow = g_Wxro + (size_t)(rr0 + bcol) * ND;
    unsigned smem_base = smem_u32(smc);

    #define PRE_ISSUE(s)                                                        \
    {                                                                           \
        unsigned stg = smem_base + ((s) % 3) * 24576u;                          \
        unsigned ab  = stg + (unsigned)(arow * 128);                            \
        unsigned bbs = stg + 16384u + (unsigned)(bcol * 128);                   \
        const float* ap = xrow + (s) * 32;                                      \
        const float* bp = wrow + (s) * 32;                                      \
        _Pragma("unroll")                                                       \
        for (int p = 0; p < 4; p++) { int qn = aq0 + p; CP16(ab + qn * 16, ap + qn * 4); } \
        _Pragma("unroll")                                                       \
        for (int p = 0; p < 2; p++) { int qn = bq0 + p; CP16(bbs + ((qn ^ bperm) << 4), bp + qn * 4); } \
        CP_COMMIT();                                                            \
    }

    int aoff[8], boff[4];
    #pragma unroll
    for (int i = 0; i < 8; i++)
        aoff[i] = (ty * 8 + i) * 128;
    #pragma unroll
    for (int j = 0; j < 4; j++) {
        int cc = tx * 4 + j;
        boff[j] = (cc * 128) ^ ((((cc ^ (cc >> 3)) & 7)) << 4);
    }

    ull acc[32];
    #pragma unroll
    for (int i = 0; i < 32; i++) acc[i] = 0ull;

    const int NS = ND / 32;
    PRE_ISSUE(0);
    PRE_ISSUE(1);
    for (int s = 0; s < NS; s++) {
        if (s + 2 < NS) { CP_WAIT1(); } else { CP_WAIT0(); }
        __syncthreads();
        if (s + 2 < NS) PRE_ISSUE(s + 2);
        const char* Ab = smc + (s % 3) * 24576;
        slab84(Ab, Ab + 16384, aoff, boff, acc);
    }
    #undef PRE_ISSUE

    int tt = r0 >> 10;
    #pragma unroll
    for (int i = 0; i < 8; i++) {
        int r = r0 + ty * 8 + i;
        int rr = rr0 + tx * 4;
        float2 s0 = unpack2(acc[i * 4 + 0]);
        float2 s1 = unpack2(acc[i * 4 + 1]);
        float2 s2 = unpack2(acc[i * 4 + 2]);
        float2 s3 = unpack2(acc[i * 4 + 3]);
        float4 v;
        v.x = s0.x + s0.y + g_biasro[rr];
        v.y = s1.x + s1.y + g_biasro[rr + 1];
        v.z = s2.x + s2.y + g_biasro[rr + 2];
        v.w = s3.x + s3.y + g_biasro[rr + 3];
        if (tt == 0) {
            v.x += g_c0ro[rr];     v.y += g_c0ro[rr + 1];
            v.z += g_c0ro[rr + 2]; v.w += g_c0ro[rr + 3];
        }
        *(float4*)(g_pre + (size_t)r * NG + rr) = v;
    }
}

// ---------------- persistent recurrence: 256 CTAs, 2/SM ----------------
// cta <128:  G1 (64 batches x 64 cols, K=128). B res 32KB, A 32KB/step.
// cta >=128: G2 K-half (32 Hg-rows x 64 cols, K=256). B res 64KB, A 32KB/step.
// smem: B @0 (64KB) | A @65536 (32KB)   request 99328 (2/SM)
__global__ __launch_bounds__(256, 2)
void recur_kernel() {
    extern __shared__ char dsm[];
    unsigned raw = smem_u32(dsm);
    unsigned db = (raw + 1023u) & ~1023u;
    char* smb = dsm + (db - raw);
    unsigned Bsm = db;
    unsigned Asm = db + 65536u;
    char* Bp = smb;
    char* Ap = smb + 65536;

    int tid = threadIdx.x;
    int cta = blockIdx.x;
    bool isG1 = cta < 128;

    // G1 mapping
    int b0  = (cta & 15) * 64;
    int rr0g1 = (cta >> 4) * 64;
    int tx = tid & 15, ty = tid >> 4;
    // G2 mapping
    int idx = cta - 128;
    int kh  = idx & 1;
    int r0  = ((idx >> 1) & 7) * 32;
    int rr0g2 = (idx >> 4) * 64;
    int lane = tid & 31, warp = tid >> 5;
    int lane7 = lane & 7;

    int rr0 = isG1 ? rr0g1 : rr0g2;

    // LSTM ownership: 2 cells per thread
    int T = cta * 256 + tid;
    int b_l = T >> 6;
    int ui = T & 63;            // unit pair index: units 2*ui, 2*ui+1; cols 8*ui..+8

    // zero h0
    *(float2*)(&g_h[0][b_l * NH + 2 * ui]) = make_float2(0.f, 0.f);

    // resident B fill
    {
        int nsl  = isG1 ? 4 : 8;
        int koff = isG1 ? 0 : (128 + kh * 256);
        for (int ci = tid; ci < nsl * 512; ci += 256) {
            int s = ci >> 9;
            int rem = ci & 511;
            int c = rem >> 3, qn = rem & 7;
            int perm = (c ^ (c >> 3)) & 7;
            CP16(Bsm + (unsigned)(s * 8192 + c * 128 + ((qn ^ perm) << 4)),
                 g_Wro + (size_t)(rr0 + c) * NK + koff + s * 32 + qn * 4);
        }
        CP_COMMIT(); CP_WAIT0();
    }
    grid_barrier();

    // compute-side constants
    int aoff[4], boff[4];
    if (isG1) {
        #pragma unroll
        for (int i = 0; i < 4; i++)
            aoff[i] = (ty * 4 + i) * 128;
        #pragma unroll
        for (int j = 0; j < 4; j++) {
            int cc = tx * 4 + j;
            boff[j] = (cc * 128) ^ ((((cc ^ (cc >> 3)) & 7)) << 4);
        }
    }
    int arow_off = lane * 128;          // G2: lane = row
    int cbase_off = warp * 8 * 128;     // G2: warp = 8-col group

    // G1 A-fill constants: 2 chunks per thread per slab
    int fr0 = tid >> 3, fq0 = tid & 7;           // entry tid
    int fr1 = (tid + 256) >> 3, fq1 = tid & 7;   // entry tid+256 (qn same)
    // G2 A-fill: 1 chunk per thread per slab, swizzled rows
    int gr = tid >> 3, gq = tid & 7;
    unsigned gsw = (unsigned)((gq ^ (gr & 7)) << 4);

    float creg[2] = {0.f, 0.f};
    float hs2[2] = {0.f, 0.f};

    for (int t = 0; t < NT; t++) {
        const float* hb = g_h[t & 1];
        float* hn = g_h[(t + 1) & 1];

        // ---- A fill: per-slab commit groups ----
        if (isG1) {
            #pragma unroll
            for (int s = 0; s < 4; s++) {
                CP16(Asm + (unsigned)(s * 8192 + fr0 * 128 + fq0 * 16),
                     hb + (size_t)(b0 + fr0) * NH + s * 32 + fq0 * 4);
                CP16(Asm + (unsigned)(s * 8192 + fr1 * 128 + fq1 * 16),
                     hb + (size_t)(b0 + fr1) * NH + s * 32 + fq1 * 4);
                CP_COMMIT();
            }
        } else {
            #pragma unroll
            for (int s = 0; s < 8; s++) {
                CP16(Asm + (unsigned)(s * 4096 + gr * 128) + gsw,
                     hb + (size_t)(r0 + gr) * 512 + kh * 256 + s * 32 + gq * 4);
                CP_COMMIT();
            }
        }

        // prefetch pre for my 2 cells (overlaps fills)
        float pr[8];
        {
            const float4* PR = (const float4*)(g_pre + ((size_t)t * NB + b_l) * NG + 8 * ui);
            *(float4*)(pr) = PR[0];
            *(float4*)(pr + 4) = PR[1];
        }

        // ---- GEMM with per-slab waits ----
        if (isG1) {
            ull acc[16];
            #pragma unroll
            for (int i = 0; i < 16; i++) acc[i] = 0ull;
            CP_WAITN(3); __syncthreads();
            slab44(Ap + 0 * 8192, Bp + 0 * 8192, aoff, boff, acc);
            CP_WAITN(2); __syncthreads();
            slab44(Ap + 1 * 8192, Bp + 1 * 8192, aoff, boff, acc);
            CP_WAITN(1); __syncthreads();
            slab44(Ap + 2 * 8192, Bp + 2 * 8192, aoff, boff, acc);
            CP_WAITN(0); __syncthreads();
            slab44(Ap + 3 * 8192, Bp + 3 * 8192, aoff, boff, acc);

            #pragma unroll
            for (int i = 0; i < 4; i++) {
                float2 s0 = unpack2(acc[i * 4 + 0]);
                float2 s1 = unpack2(acc[i * 4 + 1]);
                float2 s2 = unpack2(acc[i * 4 + 2]);
                float2 s3 = unpack2(acc[i * 4 + 3]);
                float4 v = make_float4(s0.x + s0.y, s1.x + s1.y,
                                       s2.x + s2.y, s3.x + s3.y);
                *(float4*)(g_G1 + (size_t)(b0 + ty * 4 + i) * NG + rr0 + tx * 4) = v;
            }
        } else {
            ull acc[8];
            #pragma unroll
            for (int i = 0; i < 8; i++) acc[i] = 0ull;
            CP_WAITN(7); __syncthreads();
            slab18(Ap + 0 * 4096, Bp + 0 * 8192, arow_off, lane7, cbase_off, acc);
            CP_WAITN(6); __syncthreads();
            slab18(Ap + 1 * 4096, Bp + 1 * 8192, arow_off, lane7, cbase_off, acc);
            CP_WAITN(5); __syncthreads();
            slab18(Ap + 2 * 4096, Bp + 2 * 8192, arow_off, lane7, cbase_off, acc);
            CP_WAITN(4); __syncthreads();
            slab18(Ap + 3 * 4096, Bp + 3 * 8192, arow_off, lane7, cbase_off, acc);
            CP_WAITN(3); __syncthreads();
            slab18(Ap + 4 * 4096, Bp + 4 * 8192, arow_off, lane7, cbase_off, acc);
            CP_WAITN(2); __syncthreads();
            slab18(Ap + 5 * 4096, Bp + 5 * 8192, arow_off, lane7, cbase_off, acc);
            CP_WAITN(1); __syncthreads();
            slab18(Ap + 6 * 4096, Bp + 6 * 8192, arow_off, lane7, cbase_off, acc);
            CP_WAITN(0); __syncthreads();
            slab18(Ap + 7 * 4096, Bp + 7 * 8192, arow_off, lane7, cbase_off, acc);

            float ov[8];
            #pragma unroll
            for (int j = 0; j < 8; j++) {
                float2 sj = unpack2(acc[j]);
                ov[j] = sj.x + sj.y;
            }
            float* dst = g_G2p[kh] + (size_t)(r0 + lane) * NG + rr0 + warp * 8;
            *(float4*)(dst) = make_float4(ov[0], ov[1], ov[2], ov[3]);
            *(float4*)(dst + 4) = make_float4(ov[4], ov[5], ov[6], ov[7]);
        }

        grid_barrier();

        // ---- fused LSTM: 2 cells/thread ----
        {
            const float4* V1 = (const float4*)(g_G1 + (size_t)b_l * NG + 8 * ui);
            const float4* Va = (const float4*)(g_G2p[0] + (size_t)(b_l & 255) * NG + 8 * ui);
            const float4* Vb = (const float4*)(g_G2p[1] + (size_t)(b_l & 255) * NG + 8 * ui);
            float hv[2];
            #pragma unroll
            for (int w = 0; w < 2; w++) {
                float4 a = V1[w], p0 = Va[w], p1 = Vb[w];
                float gi = pr[4 * w + 0] + a.x + p0.x + p1.x;
                float gf = pr[4 * w + 1] + a.y + p0.y + p1.y;
                float gg = pr[4 * w + 2] + a.z + p0.z + p1.z;
                float go = pr[4 * w + 3] + a.w + p0.w + p1.w;
                float cv = sig_fast(gf) * creg[w] + sig_fast(gi) * tanh_fast(gg);
                creg[w] = cv;
                hv[w] = sig_fast(go) * tanh_fast(cv);
                hs2[w] += hv[w];
            }
            *(float2*)(&hn[b_l * NH + 2 * ui]) = make_float2(hv[0], hv[1]);
        }
        if (t + 1 < NT) grid_barrier();
    }

    *(float2*)(&g_hsum[b_l * NH + 2 * ui]) = make_float2(hs2[0], hs2[1]);
}

// ---------------- final ----------------
__global__ void final_kernel(float* __restrict__ out, const float* __restrict__ fc_b) {
    int b = blockIdx.x * blockDim.x + threadIdx.x;
    if (b >= NB) return;
    #pragma unroll
    for (int o = 0; o < 2; o++) {
        const float* f = g_fA + o * NK;
        const float* hsp = g_hsum + b * NH;
        float s = 0.f;
        for (int k = 0; k < NH; k++) s += f[k] * hsp[k];
        #pragma unroll
        for (int q = 0; q < 4; q++) {
            const float* hq = g_hsum + ((4 * b + q) & 1023) * NH;
            const float* fq = f + 128 + q * 128;
            for (int m = 0; m < NH; m++) s += fq[m] * hq[m];
        }
        out[b * 2 + o] = fc_b[o] + s * (1.f / (float)NT);
    }
}

// ---------------- launch ----------------
extern "C" void kernel_launch(void* const* d_in, const int* in_sizes, int n_in,
                              void* d_out, int out_size) {
    const float* x      = (const float*)d_in[0];
    const float* memory = (const float*)d_in[1];
    const float* rv0    = (const float*)d_in[2];
    const float* W_ih   = (const float*)d_in[3];
    const float* W_hh   = (const float*)d_in[4];
    const float* b_ih   = (const float*)d_in[5];
    const float* b_hh   = (const float*)d_in[6];
    const float* fc_w   = (const float*)d_in[7];
    const float* fc_b   = (const float*)d_in[8];
    float* out = (float*)d_out;

    static bool attr_done = false;
    if (!attr_done) {
        cudaFuncSetAttribute(pre_kernel, cudaFuncAttributeMaxDynamicSharedMemorySize, 73728);
        cudaFuncSetAttribute(recur_kernel, cudaFuncAttributeMaxDynamicSharedMemorySize, 99328);
        attr_done = true;
    }

    setup_kernel<<<1, 128>>>(memory, b_ih, b_hh, rv0, W_ih);
    buildA_kernel<<<dim3(514, 7), 128>>>(W_ih, W_hh, fc_w);
    pre_kernel<<<dim3(NT * NB / 128, NG / 64), 256, 73728>>>(x);
    recur_kernel<<<NCTA, 256, 99328>>>();
    final_kernel<<<4, 256>>>(out, fc_b);
}